// round 1
// baseline (speedup 1.0000x reference)
#include <cuda_runtime.h>
#include <math.h>

#define BB 4
#define NN 4096
#define KK 16
#define EPSF 1e-12f
#define TPB 128
#define BLKS_PER_B (NN / TPB)   // 32

// scratch: kappa values for [pass][batch][point]; pass 0 = ori, pass 1 = adv
__device__ float g_kappa[2][BB][NN];

// ---------------------------------------------------------------------------
// kappa for ori point cloud with its own normals
// ---------------------------------------------------------------------------
__global__ __launch_bounds__(TPB) void kappa_ori_kernel(
    const float* __restrict__ ori, const float* __restrict__ nrm)
{
    const int b = blockIdx.x / BLKS_PER_B;
    const int q = (blockIdx.x % BLKS_PER_B) * TPB + threadIdx.x;

    __shared__ float3 sp[NN];   // 49152 bytes (exactly 48KB)
    const float* pc = ori + (size_t)b * NN * 3;
    for (int j = threadIdx.x; j < NN; j += TPB) {
        sp[j] = make_float3(pc[3 * j + 0], pc[3 * j + 1], pc[3 * j + 2]);
    }
    __syncthreads();

    const float ax = pc[3 * q + 0];
    const float ay = pc[3 * q + 1];
    const float az = pc[3 * q + 2];
    const float na = ax * ax + ay * ay + az * az;

    float bd[KK];
    int   bi[KK];
#pragma unroll
    for (int t = 0; t < KK; ++t) { bd[t] = 3.4e38f; bi[t] = 0; }
    float worst = 3.4e38f;

    for (int j = 0; j < NN; ++j) {
        float3 p = sp[j];
        float nb  = p.x * p.x + p.y * p.y + p.z * p.z;
        float dot = ax * p.x + ay * p.y + az * p.z;
        float d   = (na + nb) - 2.0f * dot;
        if (j != q && d < worst) {
            float cd = d; int ci = j;
#pragma unroll
            for (int t = 0; t < KK; ++t) {
                if (cd < bd[t]) {
                    float td = bd[t]; bd[t] = cd; cd = td;
                    int   ti = bi[t]; bi[t] = ci; ci = ti;
                }
            }
            worst = bd[KK - 1];
        }
    }

    const float* nr = nrm + (size_t)b * NN * 3;
    const float nx = nr[3 * q + 0];
    const float ny = nr[3 * q + 1];
    const float nz = nr[3 * q + 2];

    float s = 0.0f;
#pragma unroll
    for (int t = 0; t < KK; ++t) {
        float3 p = sp[bi[t]];
        float vx = p.x - ax, vy = p.y - ay, vz = p.z - az;
        float nv = sqrtf(vx * vx + vy * vy + vz * vz);
        float inv = 1.0f / (nv + EPSF);
        s += fabsf((vx * nx + vy * ny + vz * nz) * inv);
    }
    g_kappa[0][b][q] = s * (1.0f / KK);
}

// ---------------------------------------------------------------------------
// kappa for adv point cloud; normal gathered from nearest ori point
// ---------------------------------------------------------------------------
__global__ __launch_bounds__(TPB) void kappa_adv_kernel(
    const float* __restrict__ ori, const float* __restrict__ adv,
    const float* __restrict__ nrm)
{
    const int b = blockIdx.x / BLKS_PER_B;
    const int q = (blockIdx.x % BLKS_PER_B) * TPB + threadIdx.x;

    __shared__ float3 sp[NN];
    const float* pco = ori + (size_t)b * NN * 3;
    const float* pca = adv + (size_t)b * NN * 3;

    // query point (adv)
    const float ax = pca[3 * q + 0];
    const float ay = pca[3 * q + 1];
    const float az = pca[3 * q + 2];
    const float na = ax * ax + ay * ay + az * az;

    // --- phase 1: argmin over ori points -> nearest normal ---
    for (int j = threadIdx.x; j < NN; j += TPB) {
        sp[j] = make_float3(pco[3 * j + 0], pco[3 * j + 1], pco[3 * j + 2]);
    }
    __syncthreads();

    float dmin = 3.4e38f;
    int   jmin = 0;
    for (int j = 0; j < NN; ++j) {
        float3 p = sp[j];
        float nb  = p.x * p.x + p.y * p.y + p.z * p.z;
        float dot = ax * p.x + ay * p.y + az * p.z;
        float d   = (na + nb) - 2.0f * dot;
        if (d < dmin) { dmin = d; jmin = j; }
    }
    const float* nr = nrm + (size_t)b * NN * 3;
    const float nx = nr[3 * jmin + 0];
    const float ny = nr[3 * jmin + 1];
    const float nz = nr[3 * jmin + 2];
    __syncthreads();

    // --- phase 2: top-16 over adv points ---
    for (int j = threadIdx.x; j < NN; j += TPB) {
        sp[j] = make_float3(pca[3 * j + 0], pca[3 * j + 1], pca[3 * j + 2]);
    }
    __syncthreads();

    float bd[KK];
    int   bi[KK];
#pragma unroll
    for (int t = 0; t < KK; ++t) { bd[t] = 3.4e38f; bi[t] = 0; }
    float worst = 3.4e38f;

    for (int j = 0; j < NN; ++j) {
        float3 p = sp[j];
        float nb  = p.x * p.x + p.y * p.y + p.z * p.z;
        float dot = ax * p.x + ay * p.y + az * p.z;
        float d   = (na + nb) - 2.0f * dot;
        if (j != q && d < worst) {
            float cd = d; int ci = j;
#pragma unroll
            for (int t = 0; t < KK; ++t) {
                if (cd < bd[t]) {
                    float td = bd[t]; bd[t] = cd; cd = td;
                    int   ti = bi[t]; bi[t] = ci; ci = ti;
                }
            }
            worst = bd[KK - 1];
        }
    }

    float s = 0.0f;
#pragma unroll
    for (int t = 0; t < KK; ++t) {
        float3 p = sp[bi[t]];
        float vx = p.x - ax, vy = p.y - ay, vz = p.z - az;
        float nv = sqrtf(vx * vx + vy * vy + vz * vz);
        float inv = 1.0f / (nv + EPSF);
        s += fabsf((vx * nx + vy * ny + vz * nz) * inv);
    }
    g_kappa[1][b][q] = s * (1.0f / KK);
}

// ---------------------------------------------------------------------------
// per-batch std (ddof=1) of both kappa sets, then mean |std_adv - std_ori|
// ---------------------------------------------------------------------------
__global__ __launch_bounds__(256) void reduce_kernel(float* __restrict__ out)
{
    __shared__ double red[256];
    __shared__ double s_std[2][BB];
    const int tid = threadIdx.x;

    for (int p = 0; p < 2; ++p) {
        for (int b = 0; b < BB; ++b) {
            // pass 1: mean
            double s = 0.0;
            for (int i = tid; i < NN; i += 256) s += (double)g_kappa[p][b][i];
            red[tid] = s;
            __syncthreads();
            for (int st = 128; st > 0; st >>= 1) {
                if (tid < st) red[tid] += red[tid + st];
                __syncthreads();
            }
            double mean = red[0] / (double)NN;
            __syncthreads();
            // pass 2: sum of squared deviations
            double s2 = 0.0;
            for (int i = tid; i < NN; i += 256) {
                double dv = (double)g_kappa[p][b][i] - mean;
                s2 += dv * dv;
            }
            red[tid] = s2;
            __syncthreads();
            for (int st = 128; st > 0; st >>= 1) {
                if (tid < st) red[tid] += red[tid + st];
                __syncthreads();
            }
            if (tid == 0) s_std[p][b] = sqrt(red[0] / (double)(NN - 1));
            __syncthreads();
        }
    }

    if (tid == 0) {
        double acc = 0.0;
        for (int b = 0; b < BB; ++b) acc += fabs(s_std[1][b] - s_std[0][b]);
        out[0] = (float)(acc / (double)BB);
    }
}

// ---------------------------------------------------------------------------
extern "C" void kernel_launch(void* const* d_in, const int* in_sizes, int n_in,
                              void* d_out, int out_size)
{
    const float* ori = (const float*)d_in[0];
    const float* adv = (const float*)d_in[1];
    const float* nrm = (const float*)d_in[2];
    float* out = (float*)d_out;

    kappa_ori_kernel<<<BB * BLKS_PER_B, TPB>>>(ori, nrm);
    kappa_adv_kernel<<<BB * BLKS_PER_B, TPB>>>(ori, adv, nrm);
    reduce_kernel<<<1, 256>>>(out);
}

// round 3
// speedup vs baseline: 1.2913x; 1.2913x over previous
#include <cuda_runtime.h>
#include <math.h>

#define BB 4
#define NN 4096
#define KK 16
#define K17 17
#define EPSF 1e-12f
#define TPB 512
#define BLKQ 128
#define SEGS 4
#define SEGN (NN / SEGS)          // 1024
#define BLKS_PER_B (NN / BLKQ)    // 32

// scratch: kappa values for [pass][batch][point]; pass 0 = ori, pass 1 = adv
__device__ float g_kappa[2][BB][NN];

// ---- dynamic smem layout ----
// float4 tile[NN]                             : 65536 B
// float  pd[SEGS-1][BLKQ][K17]                : 26112 B
// int    pi[SEGS-1][BLKQ][K17]                : 26112 B
// float  amd[SEGS][BLKQ]                      : 2048 B
// int    ami[SEGS][BLKQ]                      : 2048 B
#define OFF_TILE 0
#define OFF_PD   (OFF_TILE + NN * 16)
#define OFF_PI   (OFF_PD + (SEGS - 1) * BLKQ * K17 * 4)
#define OFF_AMD  (OFF_PI + (SEGS - 1) * BLKQ * K17 * 4)
#define OFF_AMI  (OFF_AMD + SEGS * BLKQ * 4)
#define SMEM_TOTAL (OFF_AMI + SEGS * BLKQ * 4)

__device__ __forceinline__ void insert17(float* bd, int* bi, float d, int i)
{
#pragma unroll
    for (int t = 0; t < K17; ++t) {
        if (d < bd[t]) {
            float td = bd[t]; bd[t] = d; d = td;
            int   ti = bi[t]; bi[t] = i; i = ti;
        }
    }
}

// load a point cloud batch into the float4 tile (w = |p|^2)
__device__ __forceinline__ void load_tile(float4* tile, const float* pc, int tid)
{
    for (int j = tid; j < NN; j += TPB) {
        float x = pc[3 * j + 0];
        float y = pc[3 * j + 1];
        float z = pc[3 * j + 2];
        tile[j] = make_float4(x, y, z, x * x + y * y + z * z);
    }
}

// scan one 1024-candidate segment, maintaining partial top-17
__device__ __forceinline__ void scan_seg(const float4* __restrict__ tile, int segbase,
                                         float ax, float ay, float az, float na,
                                         float* bd, int* bi)
{
    float worst = 3.4e38f;
    const float4* seg = tile + segbase;
#pragma unroll 4
    for (int j = 0; j < SEGN; ++j) {
        float4 p = seg[j];
        float dot = fmaf(az, p.z, fmaf(ay, p.y, ax * p.x));
        float d   = fmaf(-2.0f, dot, na + p.w);
        if (d < worst) {
            insert17(bd, bi, d, segbase + j);
            worst = bd[K17 - 1];
        }
    }
}

// merge 3 other partial lists into (bd,bi), lists are sorted ascending
__device__ __forceinline__ void merge_partials(const float* pd, const int* pi, int ql,
                                               float* bd, int* bi)
{
    float worst = bd[K17 - 1];
#pragma unroll
    for (int s = 0; s < SEGS - 1; ++s) {
        const float* qd = pd + (s * BLKQ + ql) * K17;
        const int*   qi = pi + (s * BLKQ + ql) * K17;
        for (int t = 0; t < K17; ++t) {
            float d = qd[t];
            if (d >= worst) break;      // sorted -> nothing later can insert
            insert17(bd, bi, d, qi[t]);
            worst = bd[K17 - 1];
        }
    }
}

__device__ __forceinline__ float kappa_from_topk(const float4* tile,
                                                 float ax, float ay, float az,
                                                 float nx, float ny, float nz,
                                                 const int* bi)
{
    float s = 0.0f;
#pragma unroll
    for (int t = 1; t < K17; ++t) {     // drop entry 0 (self / nearest)
        float4 p = tile[bi[t]];
        float vx = p.x - ax, vy = p.y - ay, vz = p.z - az;
        float nv = sqrtf(vx * vx + vy * vy + vz * vz);
        float inv = 1.0f / (nv + EPSF);
        s += fabsf((vx * nx + vy * ny + vz * nz) * inv);
    }
    return s * (1.0f / KK);
}

// ---------------------------------------------------------------------------
// kappa for ori point cloud with its own normals
// ---------------------------------------------------------------------------
__global__ __launch_bounds__(TPB, 1) void kappa_ori_kernel(
    const float* __restrict__ ori, const float* __restrict__ nrm)
{
    extern __shared__ char smem[];
    float4* tile = (float4*)(smem + OFF_TILE);
    float*  pd   = (float*)(smem + OFF_PD);
    int*    pi   = (int*)(smem + OFF_PI);

    const int tid = threadIdx.x;
    const int ql  = tid % BLKQ;
    const int seg = tid / BLKQ;
    const int b   = blockIdx.x / BLKS_PER_B;
    const int q   = (blockIdx.x % BLKS_PER_B) * BLKQ + ql;

    const float* pc = ori + (size_t)b * NN * 3;
    load_tile(tile, pc, tid);
    __syncthreads();

    const float ax = pc[3 * q + 0];
    const float ay = pc[3 * q + 1];
    const float az = pc[3 * q + 2];
    const float na = ax * ax + ay * ay + az * az;

    float bd[K17]; int bi[K17];
#pragma unroll
    for (int t = 0; t < K17; ++t) { bd[t] = 3.4e38f; bi[t] = 0; }

    scan_seg(tile, seg * SEGN, ax, ay, az, na, bd, bi);

    // publish partials (segs 1..3)
    if (seg != 0) {
        float* qd = pd + ((seg - 1) * BLKQ + ql) * K17;
        int*   qi = pi + ((seg - 1) * BLKQ + ql) * K17;
#pragma unroll
        for (int t = 0; t < K17; ++t) { qd[t] = bd[t]; qi[t] = bi[t]; }
    }
    __syncthreads();

    if (seg == 0) {
        merge_partials(pd, pi, ql, bd, bi);
        const float* nr = nrm + (size_t)b * NN * 3;
        float nx = nr[3 * q + 0], ny = nr[3 * q + 1], nz = nr[3 * q + 2];
        g_kappa[0][b][q] = kappa_from_topk(tile, ax, ay, az, nx, ny, nz, bi);
    }
}

// ---------------------------------------------------------------------------
// kappa for adv point cloud; normal gathered from nearest ori point
// ---------------------------------------------------------------------------
__global__ __launch_bounds__(TPB, 1) void kappa_adv_kernel(
    const float* __restrict__ ori, const float* __restrict__ adv,
    const float* __restrict__ nrm)
{
    extern __shared__ char smem[];
    float4* tile = (float4*)(smem + OFF_TILE);
    float*  pd   = (float*)(smem + OFF_PD);
    int*    pi   = (int*)(smem + OFF_PI);
    float*  amd  = (float*)(smem + OFF_AMD);
    int*    ami  = (int*)(smem + OFF_AMI);

    const int tid = threadIdx.x;
    const int ql  = tid % BLKQ;
    const int seg = tid / BLKQ;
    const int b   = blockIdx.x / BLKS_PER_B;
    const int q   = (blockIdx.x % BLKS_PER_B) * BLKQ + ql;

    const float* pco = ori + (size_t)b * NN * 3;
    const float* pca = adv + (size_t)b * NN * 3;

    const float ax = pca[3 * q + 0];
    const float ay = pca[3 * q + 1];
    const float az = pca[3 * q + 2];
    const float na = ax * ax + ay * ay + az * az;

    // --- phase 1: argmin over ori points ---
    load_tile(tile, pco, tid);
    __syncthreads();

    {
        float dmin = 3.4e38f; int jmin = 0;
        const int segbase = seg * SEGN;
        const float4* sp = tile + segbase;
#pragma unroll 4
        for (int j = 0; j < SEGN; ++j) {
            float4 p = sp[j];
            float dot = fmaf(az, p.z, fmaf(ay, p.y, ax * p.x));
            float d   = fmaf(-2.0f, dot, na + p.w);
            if (d < dmin) { dmin = d; jmin = segbase + j; }
        }
        amd[seg * BLKQ + ql] = dmin;
        ami[seg * BLKQ + ql] = jmin;
    }
    __syncthreads();

    float nx = 0.f, ny = 0.f, nz = 0.f;
    if (seg == 0) {
        float best = 3.4e38f; int jm = 0;
#pragma unroll
        for (int s = 0; s < SEGS; ++s) {
            float d = amd[s * BLKQ + ql];
            if (d < best) { best = d; jm = ami[s * BLKQ + ql]; }
        }
        const float* nr = nrm + (size_t)b * NN * 3;
        nx = nr[3 * jm + 0]; ny = nr[3 * jm + 1]; nz = nr[3 * jm + 2];
    }
    __syncthreads();

    // --- phase 2: top-17 over adv points ---
    load_tile(tile, pca, tid);
    __syncthreads();

    float bd[K17]; int bi[K17];
#pragma unroll
    for (int t = 0; t < K17; ++t) { bd[t] = 3.4e38f; bi[t] = 0; }

    scan_seg(tile, seg * SEGN, ax, ay, az, na, bd, bi);

    if (seg != 0) {
        float* qd = pd + ((seg - 1) * BLKQ + ql) * K17;
        int*   qi = pi + ((seg - 1) * BLKQ + ql) * K17;
#pragma unroll
        for (int t = 0; t < K17; ++t) { qd[t] = bd[t]; qi[t] = bi[t]; }
    }
    __syncthreads();

    if (seg == 0) {
        merge_partials(pd, pi, ql, bd, bi);
        g_kappa[1][b][q] = kappa_from_topk(tile, ax, ay, az, nx, ny, nz, bi);
    }
}

// ---------------------------------------------------------------------------
// per-batch std (ddof=1) of both kappa sets, then mean |std_adv - std_ori|
// ---------------------------------------------------------------------------
__global__ __launch_bounds__(256) void reduce_kernel(float* __restrict__ out)
{
    __shared__ double red[256];
    __shared__ double s_std[2][BB];
    const int tid = threadIdx.x;

    for (int p = 0; p < 2; ++p) {
        for (int b = 0; b < BB; ++b) {
            double s = 0.0;
            for (int i = tid; i < NN; i += 256) s += (double)g_kappa[p][b][i];
            red[tid] = s;
            __syncthreads();
            for (int st = 128; st > 0; st >>= 1) {
                if (tid < st) red[tid] += red[tid + st];
                __syncthreads();
            }
            double mean = red[0] / (double)NN;
            __syncthreads();
            double s2 = 0.0;
            for (int i = tid; i < NN; i += 256) {
                double dv = (double)g_kappa[p][b][i] - mean;
                s2 += dv * dv;
            }
            red[tid] = s2;
            __syncthreads();
            for (int st = 128; st > 0; st >>= 1) {
                if (tid < st) red[tid] += red[tid + st];
                __syncthreads();
            }
            if (tid == 0) s_std[p][b] = sqrt(red[0] / (double)(NN - 1));
            __syncthreads();
        }
    }

    if (tid == 0) {
        double acc = 0.0;
        for (int b = 0; b < BB; ++b) acc += fabs(s_std[1][b] - s_std[0][b]);
        out[0] = (float)(acc / (double)BB);
    }
}

// ---------------------------------------------------------------------------
extern "C" void kernel_launch(void* const* d_in, const int* in_sizes, int n_in,
                              void* d_out, int out_size)
{
    const float* ori = (const float*)d_in[0];
    const float* adv = (const float*)d_in[1];
    const float* nrm = (const float*)d_in[2];
    float* out = (float*)d_out;

    // Unconditional + idempotent on every call: kernel_launch must do identical
    // work each invocation (no static guards), and this is capture-legal.
    cudaFuncSetAttribute(kappa_ori_kernel,
                         cudaFuncAttributeMaxDynamicSharedMemorySize, SMEM_TOTAL);
    cudaFuncSetAttribute(kappa_adv_kernel,
                         cudaFuncAttributeMaxDynamicSharedMemorySize, SMEM_TOTAL);

    kappa_ori_kernel<<<BB * BLKS_PER_B, TPB, SMEM_TOTAL>>>(ori, nrm);
    kappa_adv_kernel<<<BB * BLKS_PER_B, TPB, SMEM_TOTAL>>>(ori, adv, nrm);
    reduce_kernel<<<1, 256>>>(out);
}

// round 7
// speedup vs baseline: 2.4195x; 1.8737x over previous
#include <cuda_runtime.h>
#include <math.h>

#define BB 4
#define NN 4096
#define KK 16
#define K17 17
#define EPSF 1e-12f
#define TPB 512
#define BLKQ 128
#define SEGS 4
#define SEGN (NN / SEGS)          // 1024
#define BLKS_PER_B (NN / BLKQ)    // 32
#define CAP 192
#define BIGF 3.4e38f

// scratch: kappa values for [pass][batch][point]; pass 0 = ori, pass 1 = adv
__device__ float g_kappa[2][BB][NN];

// ---- dynamic smem layout (bytes) ----
#define OFF_TILE 0                                    // float4 [NN]          65536
#define OFF_PD   (OFF_TILE + NN * 16)                 // float [3][BLKQ][K17] 26112
#define OFF_PI   (OFF_PD + (SEGS - 1) * BLKQ * K17 * 4) // int  [3][BLKQ][K17] 26112
#define OFF_AMD  (OFF_PI + (SEGS - 1) * BLKQ * K17 * 4) // float [SEGS*BLKQ]    2048
#define OFF_AMI  (OFF_AMD + SEGS * BLKQ * 4)          // int   [SEGS*BLKQ]     2048
#define OFF_RS   (OFF_AMI + SEGS * BLKQ * 4)          // float [SEGS*BLKQ]     2048
#define SMEM_TOTAL (OFF_RS + SEGS * BLKQ * 4)         // = 123904

__device__ __forceinline__ void insert17(float* bd, int* bi, float d, int i)
{
#pragma unroll
    for (int t = 0; t < K17; ++t) {
        if (d < bd[t]) {
            float td = bd[t]; bd[t] = d; d = td;
            int   ti = bi[t]; bi[t] = i; i = ti;
        }
    }
}

// load a point cloud batch into the float4 tile (w = |p|^2) — Round-3 arithmetic
__device__ __forceinline__ void load_tile(float4* tile, const float* pc, int tid)
{
    for (int j = tid; j < NN; j += TPB) {
        float x = pc[3 * j + 0];
        float y = pc[3 * j + 1];
        float z = pc[3 * j + 2];
        tile[j] = make_float4(x, y, z, x * x + y * y + z * z);
    }
}

// Round-3 distance expression, verbatim
__device__ __forceinline__ float dref(float4 p, float ax, float ay, float az, float na)
{
    float dot = fmaf(az, p.z, fmaf(ay, p.y, ax * p.x));
    return fmaf(-2.0f, dot, na + p.w);
}

// Per-segment provable bound: 5th-smallest of 128 stride-8 samples.
// >=5 candidates in this segment are <= s4; across 4 segments >=20 are
// <= max_seg(s4) = R, hence d_(17) <= R. Filter-safe for any input.
__device__ __forceinline__ float sample_bound(
    const float4* __restrict__ tile, int segbase,
    float ax, float ay, float az, float na)
{
    float s0 = BIGF, s1 = BIGF, s2 = BIGF, s3 = BIGF, s4 = BIGF;
#pragma unroll 4
    for (int t = 0; t < 128; ++t) {
        float c = dref(tile[segbase + (t << 3)], ax, ay, az, na);
        float m;
        m = fminf(s0, c); c = fmaxf(s0, c); s0 = m;
        m = fminf(s1, c); c = fmaxf(s1, c); s1 = m;
        m = fminf(s2, c); c = fmaxf(s2, c); s2 = m;
        m = fminf(s3, c); c = fmaxf(s3, c); s3 = m;
        m = fminf(s4, c); c = fmaxf(s4, c); s4 = m;
    }
    return s4;
}

// Filtered exact scan: compact survivors (d <= R) to a local buffer, then run
// the exact insert17 over the dense buffer. Result is bit-identical to
// inserting every candidate (insertion sort is order-independent for distinct
// values; R provably bounds d_(17) from above).
__device__ __forceinline__ void scan_seg(
    const float4* __restrict__ tile, int segbase, float R,
    float ax, float ay, float az, float na,
    float* bd, int* bi)
{
    float bufd[CAP];
    int   bufj[CAP];
    int c = 0;
#pragma unroll 4
    for (int j = 0; j < SEGN; ++j) {
        float4 p = tile[segbase + j];
        float d = dref(p, ax, ay, az, na);
        if (d <= R) {
            if (c < CAP) { bufd[c] = d; bufj[c] = segbase + j; ++c; }
            else insert17(bd, bi, d, segbase + j);   // exact fallback (rare)
        }
    }
    float worst = bd[K17 - 1];
    for (int t = 0; t < c; ++t) {
        float d = bufd[t];
        if (d < worst) {
            insert17(bd, bi, d, bufj[t]);
            worst = bd[K17 - 1];
        }
    }
}

// merge 3 other partial lists into (bd,bi), lists sorted ascending — Round 3 verbatim
__device__ __forceinline__ void merge_partials(const float* pd, const int* pi, int ql,
                                               float* bd, int* bi)
{
    float worst = bd[K17 - 1];
#pragma unroll
    for (int s = 0; s < SEGS - 1; ++s) {
        const float* qd = pd + (s * BLKQ + ql) * K17;
        const int*   qi = pi + (s * BLKQ + ql) * K17;
        for (int t = 0; t < K17; ++t) {
            float d = qd[t];
            if (d >= worst) break;
            insert17(bd, bi, d, qi[t]);
            worst = bd[K17 - 1];
        }
    }
}

__device__ __forceinline__ float kappa_from_topk(const float4* tile,
                                                 float ax, float ay, float az,
                                                 float nx, float ny, float nz,
                                                 const int* bi)
{
    float s = 0.0f;
#pragma unroll
    for (int t = 1; t < K17; ++t) {     // drop entry 0 (self / nearest)
        float4 p = tile[bi[t]];
        float vx = p.x - ax, vy = p.y - ay, vz = p.z - az;
        float nv = sqrtf(vx * vx + vy * vy + vz * vz);
        float inv = 1.0f / (nv + EPSF);
        s += fabsf((vx * nx + vy * ny + vz * nz) * inv);
    }
    return s * (1.0f / KK);
}

// ---------------------------------------------------------------------------
__global__ __launch_bounds__(TPB, 1) void kappa_ori_kernel(
    const float* __restrict__ ori, const float* __restrict__ nrm)
{
    extern __shared__ char smem[];
    float4* tile = (float4*)(smem + OFF_TILE);
    float*  pd   = (float*)(smem + OFF_PD);
    int*    pi   = (int*)(smem + OFF_PI);
    float*  rs   = (float*)(smem + OFF_RS);

    const int tid = threadIdx.x;
    const int ql  = tid % BLKQ;
    const int seg = tid / BLKQ;
    const int segbase = seg * SEGN;
    const int b   = blockIdx.x / BLKS_PER_B;
    const int q   = (blockIdx.x % BLKS_PER_B) * BLKQ + ql;

    const float* pc = ori + (size_t)b * NN * 3;
    load_tile(tile, pc, tid);
    __syncthreads();

    const float ax = pc[3 * q + 0];
    const float ay = pc[3 * q + 1];
    const float az = pc[3 * q + 2];
    const float na = ax * ax + ay * ay + az * az;

    // bound exchange
    rs[seg * BLKQ + ql] = sample_bound(tile, segbase, ax, ay, az, na);
    __syncthreads();
    const float R = fmaxf(fmaxf(rs[0 * BLKQ + ql], rs[1 * BLKQ + ql]),
                          fmaxf(rs[2 * BLKQ + ql], rs[3 * BLKQ + ql]));

    float bd[K17]; int bi[K17];
#pragma unroll
    for (int t = 0; t < K17; ++t) { bd[t] = BIGF; bi[t] = 0; }

    scan_seg(tile, segbase, R, ax, ay, az, na, bd, bi);

    if (seg != 0) {
        float* qd = pd + ((seg - 1) * BLKQ + ql) * K17;
        int*   qi = pi + ((seg - 1) * BLKQ + ql) * K17;
#pragma unroll
        for (int t = 0; t < K17; ++t) { qd[t] = bd[t]; qi[t] = bi[t]; }
    }
    __syncthreads();

    if (seg == 0) {
        merge_partials(pd, pi, ql, bd, bi);
        const float* nr = nrm + (size_t)b * NN * 3;
        float nx = nr[3 * q + 0], ny = nr[3 * q + 1], nz = nr[3 * q + 2];
        g_kappa[0][b][q] = kappa_from_topk(tile, ax, ay, az, nx, ny, nz, bi);
    }
}

// ---------------------------------------------------------------------------
__global__ __launch_bounds__(TPB, 1) void kappa_adv_kernel(
    const float* __restrict__ ori, const float* __restrict__ adv,
    const float* __restrict__ nrm)
{
    extern __shared__ char smem[];
    float4* tile = (float4*)(smem + OFF_TILE);
    float*  pd   = (float*)(smem + OFF_PD);
    int*    pi   = (int*)(smem + OFF_PI);
    float*  amd  = (float*)(smem + OFF_AMD);
    int*    ami  = (int*)(smem + OFF_AMI);
    float*  rs   = (float*)(smem + OFF_RS);

    const int tid = threadIdx.x;
    const int ql  = tid % BLKQ;
    const int seg = tid / BLKQ;
    const int segbase = seg * SEGN;
    const int b   = blockIdx.x / BLKS_PER_B;
    const int q   = (blockIdx.x % BLKS_PER_B) * BLKQ + ql;

    const float* pco = ori + (size_t)b * NN * 3;
    const float* pca = adv + (size_t)b * NN * 3;

    const float ax = pca[3 * q + 0];
    const float ay = pca[3 * q + 1];
    const float az = pca[3 * q + 2];
    const float na = ax * ax + ay * ay + az * az;

    // --- phase 1: argmin over ori points -> nearest normal (Round 3 verbatim) ---
    load_tile(tile, pco, tid);
    __syncthreads();

    {
        float dmin = BIGF; int jmin = 0;
#pragma unroll 4
        for (int j = 0; j < SEGN; ++j) {
            float d = dref(tile[segbase + j], ax, ay, az, na);
            if (d < dmin) { dmin = d; jmin = segbase + j; }
        }
        amd[seg * BLKQ + ql] = dmin;
        ami[seg * BLKQ + ql] = jmin;
    }
    __syncthreads();

    float nx = 0.f, ny = 0.f, nz = 0.f;
    if (seg == 0) {
        float best = BIGF; int jm = 0;
#pragma unroll
        for (int s = 0; s < SEGS; ++s) {
            float d = amd[s * BLKQ + ql];
            if (d < best) { best = d; jm = ami[s * BLKQ + ql]; }
        }
        const float* nr = nrm + (size_t)b * NN * 3;
        nx = nr[3 * jm + 0]; ny = nr[3 * jm + 1]; nz = nr[3 * jm + 2];
    }
    __syncthreads();

    // --- phase 2: top-17 over adv points ---
    load_tile(tile, pca, tid);
    __syncthreads();

    rs[seg * BLKQ + ql] = sample_bound(tile, segbase, ax, ay, az, na);
    __syncthreads();
    const float R = fmaxf(fmaxf(rs[0 * BLKQ + ql], rs[1 * BLKQ + ql]),
                          fmaxf(rs[2 * BLKQ + ql], rs[3 * BLKQ + ql]));

    float bd[K17]; int bi[K17];
#pragma unroll
    for (int t = 0; t < K17; ++t) { bd[t] = BIGF; bi[t] = 0; }

    scan_seg(tile, segbase, R, ax, ay, az, na, bd, bi);

    if (seg != 0) {
        float* qd = pd + ((seg - 1) * BLKQ + ql) * K17;
        int*   qi = pi + ((seg - 1) * BLKQ + ql) * K17;
#pragma unroll
        for (int t = 0; t < K17; ++t) { qd[t] = bd[t]; qi[t] = bi[t]; }
    }
    __syncthreads();

    if (seg == 0) {
        merge_partials(pd, pi, ql, bd, bi);
        g_kappa[1][b][q] = kappa_from_topk(tile, ax, ay, az, nx, ny, nz, bi);
    }
}

// ---------------------------------------------------------------------------
// per-batch std (ddof=1) of both kappa sets, then mean |std_adv - std_ori|
// ---------------------------------------------------------------------------
__global__ __launch_bounds__(256) void reduce_kernel(float* __restrict__ out)
{
    __shared__ double red[256];
    __shared__ double s_std[2][BB];
    const int tid = threadIdx.x;

    for (int p = 0; p < 2; ++p) {
        for (int b = 0; b < BB; ++b) {
            double s = 0.0;
            for (int i = tid; i < NN; i += 256) s += (double)g_kappa[p][b][i];
            red[tid] = s;
            __syncthreads();
            for (int st = 128; st > 0; st >>= 1) {
                if (tid < st) red[tid] += red[tid + st];
                __syncthreads();
            }
            double mean = red[0] / (double)NN;
            __syncthreads();
            double s2 = 0.0;
            for (int i = tid; i < NN; i += 256) {
                double dv = (double)g_kappa[p][b][i] - mean;
                s2 += dv * dv;
            }
            red[tid] = s2;
            __syncthreads();
            for (int st = 128; st > 0; st >>= 1) {
                if (tid < st) red[tid] += red[tid + st];
                __syncthreads();
            }
            if (tid == 0) s_std[p][b] = sqrt(red[0] / (double)(NN - 1));
            __syncthreads();
        }
    }

    if (tid == 0) {
        double acc = 0.0;
        for (int b = 0; b < BB; ++b) acc += fabs(s_std[1][b] - s_std[0][b]);
        out[0] = (float)(acc / (double)BB);
    }
}

// ---------------------------------------------------------------------------
extern "C" void kernel_launch(void* const* d_in, const int* in_sizes, int n_in,
                              void* d_out, int out_size)
{
    const float* ori = (const float*)d_in[0];
    const float* adv = (const float*)d_in[1];
    const float* nrm = (const float*)d_in[2];
    float* out = (float*)d_out;

    cudaFuncSetAttribute(kappa_ori_kernel,
                         cudaFuncAttributeMaxDynamicSharedMemorySize, SMEM_TOTAL);
    cudaFuncSetAttribute(kappa_adv_kernel,
                         cudaFuncAttributeMaxDynamicSharedMemorySize, SMEM_TOTAL);

    kappa_ori_kernel<<<BB * BLKS_PER_B, TPB, SMEM_TOTAL>>>(ori, nrm);
    kappa_adv_kernel<<<BB * BLKS_PER_B, TPB, SMEM_TOTAL>>>(ori, adv, nrm);
    reduce_kernel<<<1, 256>>>(out);
}

// round 8
// speedup vs baseline: 2.6445x; 1.0930x over previous
#include <cuda_runtime.h>
#include <math.h>

#define BB 4
#define NN 4096
#define KK 16
#define K17 17
#define EPSF 1e-12f
#define TPB 512
#define BLKQ 128
#define SEGS 4
#define SEGN (NN / SEGS)          // 1024
#define BLKS_PER_B (NN / BLKQ)    // 32
#define CHUNK 64
#define CCAP 16
#define BIGF 3.4e38f

// scratch: kappa values for [pass][batch][point]; pass 0 = ori, pass 1 = adv
__device__ float g_kappa[2][BB][NN];

// ---- dynamic smem layout (bytes) ----
#define OFF_TILE 0                                      // float4 [NN]           65536
#define OFF_PD   (OFF_TILE + NN * 16)                   // float [3][BLKQ][K17]  26112
#define OFF_PI   (OFF_PD + (SEGS - 1) * BLKQ * K17 * 4) // u16   [3][BLKQ][K17]  13056
#define OFF_AMD  (OFF_PI + (SEGS - 1) * BLKQ * K17 * 2) // float [SEGS*BLKQ]      2048
#define OFF_AMI  (OFF_AMD + SEGS * BLKQ * 4)            // int   [SEGS*BLKQ]      2048
#define OFF_RS   (OFF_AMI + SEGS * BLKQ * 4)            // float [SEGS*BLKQ]      2048
#define SMEM_TOTAL (OFF_RS + SEGS * BLKQ * 4)           // = 110848 (~108 KB)

__device__ __forceinline__ void insert17(float* bd, int* bi, float d, int i)
{
#pragma unroll
    for (int t = 0; t < K17; ++t) {
        if (d < bd[t]) {
            float td = bd[t]; bd[t] = d; d = td;
            int   ti = bi[t]; bi[t] = i; i = ti;
        }
    }
}

// load a point cloud batch into the float4 tile (w = |p|^2) — Round-3 arithmetic
__device__ __forceinline__ void load_tile(float4* tile, const float* pc, int tid)
{
    for (int j = tid; j < NN; j += TPB) {
        float x = pc[3 * j + 0];
        float y = pc[3 * j + 1];
        float z = pc[3 * j + 2];
        tile[j] = make_float4(x, y, z, x * x + y * y + z * z);
    }
}

// Round-3 distance expression, verbatim
__device__ __forceinline__ float dref(float4 p, float ax, float ay, float az, float na)
{
    float dot = fmaf(az, p.z, fmaf(ay, p.y, ax * p.x));
    return fmaf(-2.0f, dot, na + p.w);
}

// Per-segment provable bound: 5th-smallest of 128 stride-8 samples.
// >=5 candidates in this segment are <= s4; across 4 segments >=20 are
// <= max_seg(s4) = R, hence d_(17) <= R. Filter-safe for any input.
__device__ __forceinline__ float sample_bound(
    const float4* __restrict__ tile, int segbase,
    float ax, float ay, float az, float na)
{
    float s0 = BIGF, s1 = BIGF, s2 = BIGF, s3 = BIGF, s4 = BIGF;
#pragma unroll 4
    for (int t = 0; t < 128; ++t) {
        float c = dref(tile[segbase + (t << 3)], ax, ay, az, na);
        float m;
        m = fminf(s0, c); c = fmaxf(s0, c); s0 = m;
        m = fminf(s1, c); c = fmaxf(s1, c); s1 = m;
        m = fminf(s2, c); c = fmaxf(s2, c); s2 = m;
        m = fminf(s3, c); c = fmaxf(s3, c); s3 = m;
        m = fminf(s4, c); c = fmaxf(s4, c); s4 = m;
    }
    return s4;
}

// Chunked filtered exact scan: survivors (d <= R) go to a small L1-resident
// buffer, drained after each 64-candidate chunk through the exact insert17.
// Overflow falls back to direct exact insert — bit-identical selection always.
// do_argmin: additionally track min distance from a second query (bx,by,bz,nb).
template <bool DO_ARGMIN>
__device__ __forceinline__ void scan_seg(
    const float4* __restrict__ tile, int segbase, float R,
    float ax, float ay, float az, float na,
    float bx, float by, float bz, float nb,
    float* bd, int* bi, float* dmin_out, int* jmin_out)
{
    float worst = bd[K17 - 1];
    float dmin = BIGF; int jmin = 0;
    for (int c0 = 0; c0 < SEGN; c0 += CHUNK) {
        float bufd[CCAP];
        int   bufj[CCAP];
        int c = 0;
#pragma unroll 4
        for (int j = c0; j < c0 + CHUNK; ++j) {
            float4 p = tile[segbase + j];
            float d = dref(p, ax, ay, az, na);
            if (DO_ARGMIN) {
                float d2 = dref(p, bx, by, bz, nb);
                if (d2 < dmin) { dmin = d2; jmin = segbase + j; }
            }
            if (d <= R) {
                if (c < CCAP) { bufd[c] = d; bufj[c] = segbase + j; ++c; }
                else { insert17(bd, bi, d, segbase + j); worst = bd[K17 - 1]; }
            }
        }
        for (int t = 0; t < c; ++t) {
            float d = bufd[t];
            if (d < worst) {
                insert17(bd, bi, d, bufj[t]);
                worst = bd[K17 - 1];
            }
        }
    }
    if (DO_ARGMIN) { *dmin_out = dmin; *jmin_out = jmin; }
}

// merge 3 other partial lists into (bd,bi), lists sorted ascending
__device__ __forceinline__ void merge_partials(const float* pd, const unsigned short* pi,
                                               int ql, float* bd, int* bi)
{
    float worst = bd[K17 - 1];
#pragma unroll
    for (int s = 0; s < SEGS - 1; ++s) {
        const float* qd = pd + (s * BLKQ + ql) * K17;
        const unsigned short* qi = pi + (s * BLKQ + ql) * K17;
        for (int t = 0; t < K17; ++t) {
            float d = qd[t];
            if (d >= worst) break;
            insert17(bd, bi, d, (int)qi[t]);
            worst = bd[K17 - 1];
        }
    }
}

__device__ __forceinline__ float kappa_from_topk(const float4* tile,
                                                 float ax, float ay, float az,
                                                 float nx, float ny, float nz,
                                                 const int* bi)
{
    float s = 0.0f;
#pragma unroll
    for (int t = 1; t < K17; ++t) {     // drop entry 0 (self / nearest)
        float4 p = tile[bi[t]];
        float vx = p.x - ax, vy = p.y - ay, vz = p.z - az;
        float nv = sqrtf(vx * vx + vy * vy + vz * vz);
        float inv = 1.0f / (nv + EPSF);
        s += fabsf((vx * nx + vy * ny + vz * nz) * inv);
    }
    return s * (1.0f / KK);
}

__device__ __forceinline__ void publish_partials(float* pd, unsigned short* pi,
                                                 int seg, int ql,
                                                 const float* bd, const int* bi)
{
    float* qd = pd + ((seg - 1) * BLKQ + ql) * K17;
    unsigned short* qi = pi + ((seg - 1) * BLKQ + ql) * K17;
#pragma unroll
    for (int t = 0; t < K17; ++t) { qd[t] = bd[t]; qi[t] = (unsigned short)bi[t]; }
}

// ---------------------------------------------------------------------------
// fused kernel: ori top-17 + adv argmin on the ori tile, then adv top-17
// ---------------------------------------------------------------------------
__global__ __launch_bounds__(TPB, 1) void kappa_all_kernel(
    const float* __restrict__ ori, const float* __restrict__ adv,
    const float* __restrict__ nrm)
{
    extern __shared__ char smem[];
    float4* tile = (float4*)(smem + OFF_TILE);
    float*  pd   = (float*)(smem + OFF_PD);
    unsigned short* pi = (unsigned short*)(smem + OFF_PI);
    float*  amd  = (float*)(smem + OFF_AMD);
    int*    ami  = (int*)(smem + OFF_AMI);
    float*  rs   = (float*)(smem + OFF_RS);

    const int tid = threadIdx.x;
    const int ql  = tid % BLKQ;
    const int seg = tid / BLKQ;
    const int segbase = seg * SEGN;
    const int b   = blockIdx.x / BLKS_PER_B;
    const int q   = (blockIdx.x % BLKS_PER_B) * BLKQ + ql;

    const float* pco = ori + (size_t)b * NN * 3;
    const float* pca = adv + (size_t)b * NN * 3;
    const float* nr  = nrm + (size_t)b * NN * 3;

    // queries
    const float ax = pco[3 * q + 0];            // ori query
    const float ay = pco[3 * q + 1];
    const float az = pco[3 * q + 2];
    const float na = ax * ax + ay * ay + az * az;
    const float bx = pca[3 * q + 0];            // adv query
    const float by = pca[3 * q + 1];
    const float bz = pca[3 * q + 2];
    const float nb = bx * bx + by * by + bz * bz;

    // ===================== phase A: ori tile =====================
    load_tile(tile, pco, tid);
    __syncthreads();

    rs[seg * BLKQ + ql] = sample_bound(tile, segbase, ax, ay, az, na);
    __syncthreads();
    float R = fmaxf(fmaxf(rs[0 * BLKQ + ql], rs[1 * BLKQ + ql]),
                    fmaxf(rs[2 * BLKQ + ql], rs[3 * BLKQ + ql]));

    float bd[K17]; int bi[K17];
#pragma unroll
    for (int t = 0; t < K17; ++t) { bd[t] = BIGF; bi[t] = 0; }

    float dmin; int jmin;
    scan_seg<true>(tile, segbase, R, ax, ay, az, na, bx, by, bz, nb,
                   bd, bi, &dmin, &jmin);

    amd[seg * BLKQ + ql] = dmin;
    ami[seg * BLKQ + ql] = jmin;
    if (seg != 0) publish_partials(pd, pi, seg, ql, bd, bi);
    __syncthreads();

    float nx = 0.f, ny = 0.f, nz = 0.f;
    if (seg == 0) {
        // kappa_ori: merge + epilogue (reads ori tile)
        merge_partials(pd, pi, ql, bd, bi);
        float onx = nr[3 * q + 0], ony = nr[3 * q + 1], onz = nr[3 * q + 2];
        g_kappa[0][b][q] = kappa_from_topk(tile, ax, ay, az, onx, ony, onz, bi);

        // gather nearest-ori normal for the adv query (first-min across segs)
        float best = BIGF; int jm = 0;
#pragma unroll
        for (int s = 0; s < SEGS; ++s) {
            float d = amd[s * BLKQ + ql];
            if (d < best) { best = d; jm = ami[s * BLKQ + ql]; }
        }
        nx = nr[3 * jm + 0]; ny = nr[3 * jm + 1]; nz = nr[3 * jm + 2];
    }
    __syncthreads();   // everyone done reading ori tile

    // ===================== phase B: adv tile =====================
    load_tile(tile, pca, tid);
    __syncthreads();

    rs[seg * BLKQ + ql] = sample_bound(tile, segbase, bx, by, bz, nb);
    __syncthreads();
    R = fmaxf(fmaxf(rs[0 * BLKQ + ql], rs[1 * BLKQ + ql]),
              fmaxf(rs[2 * BLKQ + ql], rs[3 * BLKQ + ql]));

#pragma unroll
    for (int t = 0; t < K17; ++t) { bd[t] = BIGF; bi[t] = 0; }

    scan_seg<false>(tile, segbase, R, bx, by, bz, nb, 0.f, 0.f, 0.f, 0.f,
                    bd, bi, &dmin, &jmin);

    if (seg != 0) publish_partials(pd, pi, seg, ql, bd, bi);
    __syncthreads();

    if (seg == 0) {
        merge_partials(pd, pi, ql, bd, bi);
        g_kappa[1][b][q] = kappa_from_topk(tile, bx, by, bz, nx, ny, nz, bi);
    }
}

// ---------------------------------------------------------------------------
// per-batch std (ddof=1) of both kappa sets, then mean |std_adv - std_ori|
// ---------------------------------------------------------------------------
__global__ __launch_bounds__(256) void reduce_kernel(float* __restrict__ out)
{
    __shared__ double red[256];
    __shared__ double s_std[2][BB];
    const int tid = threadIdx.x;

    for (int p = 0; p < 2; ++p) {
        for (int b = 0; b < BB; ++b) {
            double s = 0.0;
            for (int i = tid; i < NN; i += 256) s += (double)g_kappa[p][b][i];
            red[tid] = s;
            __syncthreads();
            for (int st = 128; st > 0; st >>= 1) {
                if (tid < st) red[tid] += red[tid + st];
                __syncthreads();
            }
            double mean = red[0] / (double)NN;
            __syncthreads();
            double s2 = 0.0;
            for (int i = tid; i < NN; i += 256) {
                double dv = (double)g_kappa[p][b][i] - mean;
                s2 += dv * dv;
            }
            red[tid] = s2;
            __syncthreads();
            for (int st = 128; st > 0; st >>= 1) {
                if (tid < st) red[tid] += red[tid + st];
                __syncthreads();
            }
            if (tid == 0) s_std[p][b] = sqrt(red[0] / (double)(NN - 1));
            __syncthreads();
        }
    }

    if (tid == 0) {
        double acc = 0.0;
        for (int b = 0; b < BB; ++b) acc += fabs(s_std[1][b] - s_std[0][b]);
        out[0] = (float)(acc / (double)BB);
    }
}

// ---------------------------------------------------------------------------
extern "C" void kernel_launch(void* const* d_in, const int* in_sizes, int n_in,
                              void* d_out, int out_size)
{
    const float* ori = (const float*)d_in[0];
    const float* adv = (const float*)d_in[1];
    const float* nrm = (const float*)d_in[2];
    float* out = (float*)d_out;

    cudaFuncSetAttribute(kappa_all_kernel,
                         cudaFuncAttributeMaxDynamicSharedMemorySize, SMEM_TOTAL);

    kappa_all_kernel<<<BB * BLKS_PER_B, TPB, SMEM_TOTAL>>>(ori, adv, nrm);
    reduce_kernel<<<1, 256>>>(out);
}

// round 9
// speedup vs baseline: 3.1788x; 1.2020x over previous
#include <cuda_runtime.h>
#include <math.h>

#define BB 4
#define NN 4096
#define KK 16
#define K17 17
#define EPSF 1e-12f
#define TPB 512
#define BLKQ 128              // smem slot capacity per block (>= max queries/block)
#define BPB 37                // blocks per batch -> grid = 4*37 = 148 = SM count
#define SEGS 4
#define SEGN (NN / SEGS)      // 1024
#define CHUNK 64
#define CCAP 16
#define BIGF 3.4e38f

// scratch: kappa values for [pass][batch][point]; pass 0 = ori, pass 1 = adv
__device__ float g_kappa[2][BB][NN];

// ---- dynamic smem layout (bytes) ----
#define OFF_TILE 0                                      // float4 [NN]           65536
#define OFF_PD   (OFF_TILE + NN * 16)                   // float [3][BLKQ][K17]  26112
#define OFF_PI   (OFF_PD + (SEGS - 1) * BLKQ * K17 * 4) // u16   [3][BLKQ][K17]  13056
#define OFF_AMD  (OFF_PI + (SEGS - 1) * BLKQ * K17 * 2) // float [SEGS*BLKQ]      2048
#define OFF_AMI  (OFF_AMD + SEGS * BLKQ * 4)            // int   [SEGS*BLKQ]      2048
#define OFF_RS   (OFF_AMI + SEGS * BLKQ * 4)            // float [SEGS*BLKQ]      2048
#define SMEM_TOTAL (OFF_RS + SEGS * BLKQ * 4)           // = 110848 (~108 KB)

__device__ __forceinline__ void insert17(float* bd, int* bi, float d, int i)
{
#pragma unroll
    for (int t = 0; t < K17; ++t) {
        if (d < bd[t]) {
            float td = bd[t]; bd[t] = d; d = td;
            int   ti = bi[t]; bi[t] = i; i = ti;
        }
    }
}

// load a point cloud batch into the float4 tile (w = |p|^2)
__device__ __forceinline__ void load_tile(float4* tile, const float* pc, int tid)
{
    for (int j = tid; j < NN; j += TPB) {
        float x = pc[3 * j + 0];
        float y = pc[3 * j + 1];
        float z = pc[3 * j + 2];
        tile[j] = make_float4(x, y, z, x * x + y * y + z * z);
    }
}

// Round-3 distance expression, verbatim
__device__ __forceinline__ float dref(float4 p, float ax, float ay, float az, float na)
{
    float dot = fmaf(az, p.z, fmaf(ay, p.y, ax * p.x));
    return fmaf(-2.0f, dot, na + p.w);
}

// Per-segment provable bound: 5th-smallest of 128 stride-8 samples.
// >=5 candidates/segment are <= s4 => >=20 total <= max_seg(s4) = R => d_(17) <= R.
__device__ __forceinline__ float sample_bound(
    const float4* __restrict__ tile, int segbase,
    float ax, float ay, float az, float na)
{
    float s0 = BIGF, s1 = BIGF, s2 = BIGF, s3 = BIGF, s4 = BIGF;
#pragma unroll 4
    for (int t = 0; t < 128; ++t) {
        float c = dref(tile[segbase + (t << 3)], ax, ay, az, na);
        float m;
        m = fminf(s0, c); c = fmaxf(s0, c); s0 = m;
        m = fminf(s1, c); c = fmaxf(s1, c); s1 = m;
        m = fminf(s2, c); c = fmaxf(s2, c); s2 = m;
        m = fminf(s3, c); c = fmaxf(s3, c); s3 = m;
        m = fminf(s4, c); c = fmaxf(s4, c); s4 = m;
    }
    return s4;
}

// Chunked filtered exact scan. Buffer filter uses lim = min(R, worst): anything
// >= worst can never pass the strict '<' insert, and R provably covers d_(17),
// so selection stays bit-identical while buffered survivors shrink as worst
// tightens. Overflow falls back to direct exact insert.
template <bool DO_ARGMIN>
__device__ __forceinline__ void scan_seg(
    const float4* __restrict__ tile, int segbase, float R,
    float ax, float ay, float az, float na,
    float bx, float by, float bz, float nb,
    float* bd, int* bi, float* dmin_out, int* jmin_out)
{
    float worst = bd[K17 - 1];
    float lim = fminf(R, worst);
    float dmin = BIGF; int jmin = 0;
    for (int c0 = 0; c0 < SEGN; c0 += CHUNK) {
        float bufd[CCAP];
        int   bufj[CCAP];
        int c = 0;
#pragma unroll 4
        for (int j = c0; j < c0 + CHUNK; ++j) {
            float4 p = tile[segbase + j];
            float d = dref(p, ax, ay, az, na);
            if (DO_ARGMIN) {
                float d2 = dref(p, bx, by, bz, nb);
                if (d2 < dmin) { dmin = d2; jmin = segbase + j; }
            }
            if (d <= lim) {
                if (c < CCAP) { bufd[c] = d; bufj[c] = segbase + j; ++c; }
                else { insert17(bd, bi, d, segbase + j); worst = bd[K17 - 1]; }
            }
        }
        for (int t = 0; t < c; ++t) {
            float d = bufd[t];
            if (d < worst) {
                insert17(bd, bi, d, bufj[t]);
                worst = bd[K17 - 1];
            }
        }
        lim = fminf(R, worst);
    }
    if (DO_ARGMIN) { *dmin_out = dmin; *jmin_out = jmin; }
}

// merge 3 other partial lists into (bd,bi), lists sorted ascending
__device__ __forceinline__ void merge_partials(const float* pd, const unsigned short* pi,
                                               int ql, float* bd, int* bi)
{
    float worst = bd[K17 - 1];
#pragma unroll
    for (int s = 0; s < SEGS - 1; ++s) {
        const float* qd = pd + (s * BLKQ + ql) * K17;
        const unsigned short* qi = pi + (s * BLKQ + ql) * K17;
        for (int t = 0; t < K17; ++t) {
            float d = qd[t];
            if (d >= worst) break;
            insert17(bd, bi, d, (int)qi[t]);
            worst = bd[K17 - 1];
        }
    }
}

__device__ __forceinline__ float kappa_from_topk(const float4* tile,
                                                 float ax, float ay, float az,
                                                 float nx, float ny, float nz,
                                                 const int* bi)
{
    float s = 0.0f;
#pragma unroll
    for (int t = 1; t < K17; ++t) {     // drop entry 0 (self / nearest)
        float4 p = tile[bi[t]];
        float vx = p.x - ax, vy = p.y - ay, vz = p.z - az;
        float nv = sqrtf(vx * vx + vy * vy + vz * vz);
        float inv = 1.0f / (nv + EPSF);
        s += fabsf((vx * nx + vy * ny + vz * nz) * inv);
    }
    return s * (1.0f / KK);
}

__device__ __forceinline__ void publish_partials(float* pd, unsigned short* pi,
                                                 int seg, int ql,
                                                 const float* bd, const int* bi)
{
    float* qd = pd + ((seg - 1) * BLKQ + ql) * K17;
    unsigned short* qi = pi + ((seg - 1) * BLKQ + ql) * K17;
#pragma unroll
    for (int t = 0; t < K17; ++t) { qd[t] = bd[t]; qi[t] = (unsigned short)bi[t]; }
}

// ---------------------------------------------------------------------------
// fused kernel: ori top-17 + adv argmin on the ori tile, then adv top-17.
// Grid = BB * BPB = 148 blocks; block i of a batch covers queries
// [i*NN/BPB, (i+1)*NN/BPB)  (110 or 111 queries; slots up to BLKQ=128).
// ---------------------------------------------------------------------------
__global__ __launch_bounds__(TPB, 1) void kappa_all_kernel(
    const float* __restrict__ ori, const float* __restrict__ adv,
    const float* __restrict__ nrm)
{
    extern __shared__ char smem[];
    float4* tile = (float4*)(smem + OFF_TILE);
    float*  pd   = (float*)(smem + OFF_PD);
    unsigned short* pi = (unsigned short*)(smem + OFF_PI);
    float*  amd  = (float*)(smem + OFF_AMD);
    int*    ami  = (int*)(smem + OFF_AMI);
    float*  rs   = (float*)(smem + OFF_RS);

    const int tid = threadIdx.x;
    const int ql  = tid % BLKQ;
    const int seg = tid / BLKQ;
    const int segbase = seg * SEGN;
    const int b   = blockIdx.x / BPB;
    const int blk = blockIdx.x % BPB;
    const int q0    = (blk * NN) / BPB;
    const int q1    = ((blk + 1) * NN) / BPB;
    const int count = q1 - q0;                 // 110 or 111
    const int q   = q0 + ql;
    const int qe  = (ql < count) ? q : q0;     // clamped for loads
    const bool active = (ql < count);

    const float* pco = ori + (size_t)b * NN * 3;
    const float* pca = adv + (size_t)b * NN * 3;
    const float* nr  = nrm + (size_t)b * NN * 3;

    // queries (clamped index for inactive slots; they never write)
    const float ax = pco[3 * qe + 0];
    const float ay = pco[3 * qe + 1];
    const float az = pco[3 * qe + 2];
    const float na = ax * ax + ay * ay + az * az;
    const float bx = pca[3 * qe + 0];
    const float by = pca[3 * qe + 1];
    const float bz = pca[3 * qe + 2];
    const float nb = bx * bx + by * by + bz * bz;

    // ===================== phase A: ori tile =====================
    load_tile(tile, pco, tid);
    __syncthreads();

    rs[seg * BLKQ + ql] = sample_bound(tile, segbase, ax, ay, az, na);
    __syncthreads();
    float R = fmaxf(fmaxf(rs[0 * BLKQ + ql], rs[1 * BLKQ + ql]),
                    fmaxf(rs[2 * BLKQ + ql], rs[3 * BLKQ + ql]));

    float bd[K17]; int bi[K17];
#pragma unroll
    for (int t = 0; t < K17; ++t) { bd[t] = BIGF; bi[t] = 0; }

    float dmin; int jmin;
    scan_seg<true>(tile, segbase, R, ax, ay, az, na, bx, by, bz, nb,
                   bd, bi, &dmin, &jmin);

    amd[seg * BLKQ + ql] = dmin;
    ami[seg * BLKQ + ql] = jmin;
    if (seg != 0) publish_partials(pd, pi, seg, ql, bd, bi);
    __syncthreads();

    float nx = 0.f, ny = 0.f, nz = 0.f;
    if (seg == 0) {
        merge_partials(pd, pi, ql, bd, bi);
        if (active) {
            float onx = nr[3 * q + 0], ony = nr[3 * q + 1], onz = nr[3 * q + 2];
            g_kappa[0][b][q] = kappa_from_topk(tile, ax, ay, az, onx, ony, onz, bi);
        }
        // gather nearest-ori normal for the adv query (first-min across segs)
        float best = BIGF; int jm = 0;
#pragma unroll
        for (int s = 0; s < SEGS; ++s) {
            float d = amd[s * BLKQ + ql];
            if (d < best) { best = d; jm = ami[s * BLKQ + ql]; }
        }
        nx = nr[3 * jm + 0]; ny = nr[3 * jm + 1]; nz = nr[3 * jm + 2];
    }
    __syncthreads();   // everyone done reading ori tile

    // ===================== phase B: adv tile =====================
    load_tile(tile, pca, tid);
    __syncthreads();

    rs[seg * BLKQ + ql] = sample_bound(tile, segbase, bx, by, bz, nb);
    __syncthreads();
    R = fmaxf(fmaxf(rs[0 * BLKQ + ql], rs[1 * BLKQ + ql]),
              fmaxf(rs[2 * BLKQ + ql], rs[3 * BLKQ + ql]));

#pragma unroll
    for (int t = 0; t < K17; ++t) { bd[t] = BIGF; bi[t] = 0; }

    scan_seg<false>(tile, segbase, R, bx, by, bz, nb, 0.f, 0.f, 0.f, 0.f,
                    bd, bi, &dmin, &jmin);

    if (seg != 0) publish_partials(pd, pi, seg, ql, bd, bi);
    __syncthreads();

    if (seg == 0 && active) {
        merge_partials(pd, pi, ql, bd, bi);
        g_kappa[1][b][q] = kappa_from_topk(tile, bx, by, bz, nx, ny, nz, bi);
    }
}

// ---------------------------------------------------------------------------
// parallel reduce: 8 groups of 128 threads, one per (pass, batch); then the
// mean |std_adv - std_ori|. Same double-precision two-pass math as before.
// ---------------------------------------------------------------------------
__global__ __launch_bounds__(1024) void reduce_kernel(float* __restrict__ out)
{
    __shared__ double red[1024];
    __shared__ double s_std[8];
    const int tid = threadIdx.x;
    const int g = tid >> 7;        // group 0..7
    const int l = tid & 127;       // lane in group
    const int p = g >> 2;          // pass
    const int b = g & 3;           // batch

    // pass 1: mean
    double s = 0.0;
    for (int i = l; i < NN; i += 128) s += (double)g_kappa[p][b][i];
    red[tid] = s;
    __syncthreads();
    for (int st = 64; st > 0; st >>= 1) {
        if (l < st) red[tid] += red[tid + st];
        __syncthreads();
    }
    double mean = red[g << 7] / (double)NN;
    __syncthreads();

    // pass 2: sum of squared deviations
    double s2 = 0.0;
    for (int i = l; i < NN; i += 128) {
        double dv = (double)g_kappa[p][b][i] - mean;
        s2 += dv * dv;
    }
    red[tid] = s2;
    __syncthreads();
    for (int st = 64; st > 0; st >>= 1) {
        if (l < st) red[tid] += red[tid + st];
        __syncthreads();
    }
    if (l == 0) s_std[g] = sqrt(red[tid] / (double)(NN - 1));
    __syncthreads();

    if (tid == 0) {
        double acc = 0.0;
        for (int bb = 0; bb < BB; ++bb) acc += fabs(s_std[4 + bb] - s_std[bb]);
        out[0] = (float)(acc / (double)BB);
    }
}

// ---------------------------------------------------------------------------
extern "C" void kernel_launch(void* const* d_in, const int* in_sizes, int n_in,
                              void* d_out, int out_size)
{
    const float* ori = (const float*)d_in[0];
    const float* adv = (const float*)d_in[1];
    const float* nrm = (const float*)d_in[2];
    float* out = (float*)d_out;

    cudaFuncSetAttribute(kappa_all_kernel,
                         cudaFuncAttributeMaxDynamicSharedMemorySize, SMEM_TOTAL);

    kappa_all_kernel<<<BB * BPB, TPB, SMEM_TOTAL>>>(ori, adv, nrm);
    reduce_kernel<<<1, 1024>>>(out);
}